// round 11
// baseline (speedup 1.0000x reference)
#include <cuda_runtime.h>
#include <cuda_bf16.h>
#include <cstdint>
#include <cstddef>

#define IN_DIM   512
#define HID      256
#define BM       64
#define KB       64      // K per stage
#define NS       8       // IN_DIM / KB
#define NTHREADS 256

// per-node scalar s[n] = relu(emb[n] @ W + b) . w_sym
__device__ float g_s[50176];
// W pre-converted to bf16, same [IN_DIM][HID] layout
__device__ __nv_bfloat16 g_Wb[IN_DIM * HID];

// ---- smem layout (bytes) ----
#define OFF_A      0          // 2 x (64 rows x 128B)   = 16384
#define OFF_B      16384      // 2 x (64 rows x 512B)   = 65536
#define OFF_BW     81920      // float2[256]            = 2048
#define OFF_RED    83968      // float[64]              = 256
#define SMEM_TOTAL 84224

__device__ __forceinline__ uint32_t smem_u32(const void* p) {
    uint32_t a;
    asm("{ .reg .u64 t; cvta.to.shared.u64 t, %1; cvt.u32.u64 %0, t; }" : "=r"(a) : "l"(p));
    return a;
}
__device__ __forceinline__ void ldsm_x4(uint32_t* r, uint32_t addr) {
    asm volatile("ldmatrix.sync.aligned.m8n8.x4.shared.b16 {%0,%1,%2,%3}, [%4];"
                 : "=r"(r[0]), "=r"(r[1]), "=r"(r[2]), "=r"(r[3]) : "r"(addr));
}
__device__ __forceinline__ void ldsm_x4t(uint32_t* r, uint32_t addr) {
    asm volatile("ldmatrix.sync.aligned.m8n8.x4.trans.shared.b16 {%0,%1,%2,%3}, [%4];"
                 : "=r"(r[0]), "=r"(r[1]), "=r"(r[2]), "=r"(r[3]) : "r"(addr));
}
__device__ __forceinline__ void mma16816(float* c, const uint32_t* a, uint32_t b0, uint32_t b1) {
    asm volatile(
        "mma.sync.aligned.m16n8k16.row.col.f32.bf16.bf16.f32 "
        "{%0,%1,%2,%3}, {%4,%5,%6,%7}, {%8,%9}, {%0,%1,%2,%3};"
        : "+f"(c[0]), "+f"(c[1]), "+f"(c[2]), "+f"(c[3])
        : "r"(a[0]), "r"(a[1]), "r"(a[2]), "r"(a[3]), "r"(b0), "r"(b1));
}
__device__ __forceinline__ void cp16(uint32_t dst, const void* src) {
    asm volatile("cp.async.cg.shared.global [%0], [%1], 16;" :: "r"(dst), "l"(src));
}
#define CP_COMMIT() asm volatile("cp.async.commit_group;" ::: "memory")
#define CP_WAIT(N)  asm volatile("cp.async.wait_group %0;" :: "n"(N) : "memory")

__device__ __forceinline__ uint32_t pack_bf2(float lo, float hi) {
    return (uint32_t)__bfloat16_as_ushort(__float2bfloat16_rn(hi)) << 16
         | (uint32_t)__bfloat16_as_ushort(__float2bfloat16_rn(lo));
}

__global__ void convert_W(const float4* __restrict__ W4) {
    const int i = blockIdx.x * blockDim.x + threadIdx.x;
    if (i < IN_DIM * HID / 4) {
        const float4 v = W4[i];
        uint2 o;
        o.x = pack_bf2(v.x, v.y);
        o.y = pack_bf2(v.z, v.w);
        *reinterpret_cast<uint2*>(&g_Wb[i * 4]) = o;
    }
}

__global__ void __launch_bounds__(NTHREADS, 2)
node_kernel(const float* __restrict__ emb,
            const float* __restrict__ bias,
            const float* __restrict__ We,
            int nn) {
    extern __shared__ char smraw[];
    const uint32_t smem = smem_u32(smraw);
    const int tid  = threadIdx.x;
    const int lane = tid & 31;
    const int wid  = tid >> 5;     // 0..7
    const int wm   = wid >> 2;     // 0..1  -> rows wm*32..
    const int wn   = wid & 3;      // 0..3  -> cols wn*64..
    const int row0 = blockIdx.x * BM;

    if (tid < 64) *reinterpret_cast<float*>(smraw + OFF_RED + tid * 4) = 0.f;
    {
        float2 v; v.x = bias[tid]; v.y = 0.5f * (We[tid] + We[tid + HID]);
        *reinterpret_cast<float2*>(smraw + OFF_BW + tid * 8) = v;
    }

    // ---- stage loaders ----
    float4 ra[2][2];   // A staging: 2 chunks x 8 floats

    auto loadA = [&](int s) {
        #pragma unroll
        for (int i = 0; i < 2; ++i) {
            const int flat = tid + i * NTHREADS;       // 0..511
            const int m = flat >> 3, c = flat & 7;     // row, 8-elem chunk
            const int gr = row0 + m;
            if (gr < nn) {
                const float* p = &emb[(size_t)gr * IN_DIM + s * KB + c * 8];
                ra[i][0] = *reinterpret_cast<const float4*>(p);
                ra[i][1] = *reinterpret_cast<const float4*>(p + 4);
            } else {
                ra[i][0] = make_float4(0.f, 0.f, 0.f, 0.f);
                ra[i][1] = make_float4(0.f, 0.f, 0.f, 0.f);
            }
        }
    };
    auto stsA = [&](int buf) {
        #pragma unroll
        for (int i = 0; i < 2; ++i) {
            const int flat = tid + i * NTHREADS;
            const int m = flat >> 3, c = flat & 7;
            uint4 t;
            t.x = pack_bf2(ra[i][0].x, ra[i][0].y);
            t.y = pack_bf2(ra[i][0].z, ra[i][0].w);
            t.z = pack_bf2(ra[i][1].x, ra[i][1].y);
            t.w = pack_bf2(ra[i][1].z, ra[i][1].w);
            const uint32_t off = OFF_A + buf * 8192 + m * 128 + ((c ^ (m & 7)) << 4);
            *reinterpret_cast<uint4*>(smraw + off) = t;
        }
    };
    auto cpB = [&](int s, int buf) {
        #pragma unroll
        for (int i = 0; i < 8; ++i) {
            const int flat = tid + i * NTHREADS;       // 0..2047
            const int kr = flat >> 5, ch = flat & 31;  // k-row, 8-elem chunk
            const uint32_t dst = smem + OFF_B + buf * 32768 + kr * 512 + ((ch ^ (kr & 7)) << 4);
            cp16(dst, &g_Wb[(size_t)(s * KB + kr) * HID + ch * 8]);
        }
        CP_COMMIT();
    };

    float acc[2][8][4];
    #pragma unroll
    for (int i = 0; i < 2; ++i)
        #pragma unroll
        for (int j = 0; j < 8; ++j)
            acc[i][j][0] = acc[i][j][1] = acc[i][j][2] = acc[i][j][3] = 0.f;

    // ---- prologue ----
    cpB(0, 0);
    cpB(1, 1);
    loadA(0); stsA(0);
    loadA(1);
    CP_WAIT(1);          // B(0) complete (B(1) may be in flight)
    __syncthreads();

    const int lr  = (lane & 7) + (lane & 8);   // ldmatrix row-within-pair
    const int lhi = (lane >> 4) & 1;           // second 8-chunk select

    #pragma unroll 1
    for (int s = 0; s < NS; ++s) {
        if (s + 1 < NS) stsA((s + 1) & 1);     // A buf (s+1)&1 last read in stage s-1
        if (s + 2 < NS) loadA(s + 2);

        const uint32_t aBase = smem + OFF_A + (s & 1) * 8192;
        const uint32_t bBase = smem + OFF_B + (s & 1) * 32768;

        #pragma unroll
        for (int kk = 0; kk < 4; ++kk) {
            const int k0 = kk * 16;
            uint32_t a[2][4];
            #pragma unroll
            for (int i = 0; i < 2; ++i) {
                const int mr = wm * 32 + i * 16 + lr;
                const int kc = (k0 >> 3) + lhi;
                ldsm_x4(a[i], aBase + mr * 128 + ((kc ^ (mr & 7)) << 4));
            }
            uint32_t b[4][4];
            #pragma unroll
            for (int j = 0; j < 4; ++j) {
                const int kr = k0 + lr;
                const int nc = wn * 8 + j * 2 + lhi;
                ldsm_x4t(b[j], bBase + kr * 512 + ((nc ^ (kr & 7)) << 4));
            }
            #pragma unroll
            for (int i = 0; i < 2; ++i)
                #pragma unroll
                for (int j = 0; j < 4; ++j) {
                    mma16816(acc[i][j * 2 + 0], a[i], b[j][0], b[j][1]);
                    mma16816(acc[i][j * 2 + 1], a[i], b[j][2], b[j][3]);
                }
        }

        if (s + 1 < NS) {
            __syncthreads();                    // all warps done reading B buf s&1
            if (s + 2 < NS) {
                cpB(s + 2, s & 1);              // refill the buffer just released
                CP_WAIT(1);                     // B(s+1) complete
            } else {
                CP_WAIT(0);                     // last pending = B(s+1)
            }
            __syncthreads();                    // B(s+1) visible to all
        }
    }

    // ---- epilogue: p[m] = sum_n relu(D[m][n]+bias[n])*w_sym[n] ----
    const float2* bw = reinterpret_cast<const float2*>(smraw + OFF_BW);
    float* red = reinterpret_cast<float*>(smraw + OFF_RED);
    #pragma unroll
    for (int i = 0; i < 2; ++i) {
        float p0 = 0.f, p1 = 0.f;
        #pragma unroll
        for (int t = 0; t < 8; ++t) {
            const int ncol = wn * 64 + t * 8 + (lane & 3) * 2;
            const float2 w0 = bw[ncol], w1 = bw[ncol + 1];
            const float* c = acc[i][t];
            p0 += fmaxf(c[0] + w0.x, 0.f) * w0.y + fmaxf(c[1] + w1.x, 0.f) * w1.y;
            p1 += fmaxf(c[2] + w0.x, 0.f) * w0.y + fmaxf(c[3] + w1.x, 0.f) * w1.y;
        }
        p0 += __shfl_xor_sync(0xffffffffu, p0, 1);
        p0 += __shfl_xor_sync(0xffffffffu, p0, 2);
        p1 += __shfl_xor_sync(0xffffffffu, p1, 1);
        p1 += __shfl_xor_sync(0xffffffffu, p1, 2);
        if ((lane & 3) == 0) {
            const int r = wm * 32 + i * 16 + (lane >> 2);
            atomicAdd(&red[r], p0);
            atomicAdd(&red[r + 8], p1);
        }
    }
    __syncthreads();
    if (tid < BM) {
        const int gr = row0 + tid;
        if (gr < nn) g_s[gr] = red[tid];
    }
}

// sigmoid(log(eps/(1-eps)) + raw) == eps / (eps + (1-eps)*exp(-raw))
__global__ void edge_kernel(const int* __restrict__ e0,
                            const int* __restrict__ e1,
                            const float* __restrict__ u,
                            const float* __restrict__ be,
                            float* __restrict__ out,
                            int E) {
    const int i = blockIdx.x * blockDim.x + threadIdx.x;
    const int nv = E >> 2;
    if (i >= nv) {
        if (i == nv) {
            const float bb = be[0];
            for (int k = nv * 4; k < E; ++k) {
                const float raw = g_s[e0[k]] + g_s[e1[k]] + bb;
                const float uu = u[k];
                const float eps = fmaf(-0.9998f, uu, 0.9999f);
                const float ome = fmaf(0.9998f, uu, 0.0001f);
                out[k] = eps / fmaf(ome, __expf(-raw), eps);
            }
        }
        return;
    }
    const int4   a  = reinterpret_cast<const int4*>(e0)[i];
    const int4   b  = reinterpret_cast<const int4*>(e1)[i];
    const float4 uu = reinterpret_cast<const float4*>(u)[i];
    const float  bb = be[0];
    float4 r;
    {
        const float raw = g_s[a.x] + g_s[b.x] + bb;
        const float eps = fmaf(-0.9998f, uu.x, 0.9999f);
        const float ome = fmaf(0.9998f, uu.x, 0.0001f);
        r.x = eps / fmaf(ome, __expf(-raw), eps);
    }
    {
        const float raw = g_s[a.y] + g_s[b.y] + bb;
        const float eps = fmaf(-0.9998f, uu.y, 0.9999f);
        const float ome = fmaf(0.9998f, uu.y, 0.0001f);
        r.y = eps / fmaf(ome, __expf(-raw), eps);
    }
    {
        const float raw = g_s[a.z] + g_s[b.z] + bb;
        const float eps = fmaf(-0.9998f, uu.z, 0.9999f);
        const float ome = fmaf(0.9998f, uu.z, 0.0001f);
        r.z = eps / fmaf(ome, __expf(-raw), eps);
    }
    {
        const float raw = g_s[a.w] + g_s[b.w] + bb;
        const float eps = fmaf(-0.9998f, uu.w, 0.9999f);
        const float ome = fmaf(0.9998f, uu.w, 0.0001f);
        r.w = eps / fmaf(ome, __expf(-raw), eps);
    }
    reinterpret_cast<float4*>(out)[i] = r;
}

extern "C" void kernel_launch(void* const* d_in, const int* in_sizes, int n_in,
                              void* d_out, int out_size) {
    const float* emb   = (const float*)d_in[0];
    const int*   edges = (const int*)d_in[1];     // int32 (JAX x64 disabled)
    const float* u     = (const float*)d_in[2];
    const float* W     = (const float*)d_in[3];
    const float* b     = (const float*)d_in[4];
    const float* We    = (const float*)d_in[5];
    const float* be    = (const float*)d_in[6];
    float*       out   = (float*)d_out;

    const int nn = in_sizes[0] / IN_DIM;   // 50000
    const int E  = in_sizes[2];            // 800000

    convert_W<<<(IN_DIM * HID / 4 + 255) / 256, 256>>>((const float4*)W);

    cudaFuncSetAttribute(node_kernel, cudaFuncAttributeMaxDynamicSharedMemorySize, SMEM_TOTAL);
    node_kernel<<<(nn + BM - 1) / BM, NTHREADS, SMEM_TOTAL>>>(emb, b, We, nn);

    const int nv = (E >> 2) + 1;
    edge_kernel<<<(nv + 255) / 256, 256>>>(edges, edges + E, u, be, out, E);
}

// round 15
// speedup vs baseline: 1.4287x; 1.4287x over previous
#include <cuda_runtime.h>
#include <cuda_bf16.h>
#include <cstdint>
#include <cstddef>

#define IN_DIM   512
#define HID      256
#define BM       128
#define KB       64      // K per stage
#define NS       8       // IN_DIM / KB
#define NTHREADS 512

// per-node scalar s[n] = relu(emb[n] @ W + b) . w_sym
__device__ float g_s[50176];
// W pre-converted to bf16, same [IN_DIM][HID] layout
__device__ __nv_bfloat16 g_Wb[IN_DIM * HID];

// ---- smem layout (bytes) ----
#define OFF_ABF    0          // 2 x (128 rows x 128B)  = 32768  (bf16, swizzled)
#define OFF_B      32768      // 3 x (64 rows x 512B)   = 98304  (bf16, swizzled)
#define OFF_AF     131072     // 2 x (128 rows x 256B)  = 65536  (fp32 staging)
#define OFF_BW     196608     // float2[256]            = 2048
#define OFF_RED    198656     // float[128]             = 512
#define SMEM_TOTAL 199168

__device__ __forceinline__ uint32_t smem_u32(const void* p) {
    uint32_t a;
    asm("{ .reg .u64 t; cvta.to.shared.u64 t, %1; cvt.u32.u64 %0, t; }" : "=r"(a) : "l"(p));
    return a;
}
__device__ __forceinline__ void ldsm_x4(uint32_t* r, uint32_t addr) {
    asm volatile("ldmatrix.sync.aligned.m8n8.x4.shared.b16 {%0,%1,%2,%3}, [%4];"
                 : "=r"(r[0]), "=r"(r[1]), "=r"(r[2]), "=r"(r[3]) : "r"(addr));
}
__device__ __forceinline__ void ldsm_x4t(uint32_t* r, uint32_t addr) {
    asm volatile("ldmatrix.sync.aligned.m8n8.x4.trans.shared.b16 {%0,%1,%2,%3}, [%4];"
                 : "=r"(r[0]), "=r"(r[1]), "=r"(r[2]), "=r"(r[3]) : "r"(addr));
}
__device__ __forceinline__ void mma16816(float* c, const uint32_t* a, uint32_t b0, uint32_t b1) {
    asm volatile(
        "mma.sync.aligned.m16n8k16.row.col.f32.bf16.bf16.f32 "
        "{%0,%1,%2,%3}, {%4,%5,%6,%7}, {%8,%9}, {%0,%1,%2,%3};"
        : "+f"(c[0]), "+f"(c[1]), "+f"(c[2]), "+f"(c[3])
        : "r"(a[0]), "r"(a[1]), "r"(a[2]), "r"(a[3]), "r"(b0), "r"(b1));
}
__device__ __forceinline__ void cp16(uint32_t dst, const void* src) {
    asm volatile("cp.async.cg.shared.global [%0], [%1], 16;" :: "r"(dst), "l"(src));
}
#define CP_COMMIT() asm volatile("cp.async.commit_group;" ::: "memory")
#define CP_WAIT(N)  asm volatile("cp.async.wait_group %0;" :: "n"(N) : "memory")

__device__ __forceinline__ uint32_t pack_bf2(float lo, float hi) {
    return (uint32_t)__bfloat16_as_ushort(__float2bfloat16_rn(hi)) << 16
         | (uint32_t)__bfloat16_as_ushort(__float2bfloat16_rn(lo));
}

__global__ void convert_W(const float4* __restrict__ W4) {
    const int i = blockIdx.x * blockDim.x + threadIdx.x;
    if (i < IN_DIM * HID / 4) {
        const float4 v = W4[i];
        uint2 o;
        o.x = pack_bf2(v.x, v.y);
        o.y = pack_bf2(v.z, v.w);
        *reinterpret_cast<uint2*>(&g_Wb[i * 4]) = o;
    }
}

__global__ void __launch_bounds__(NTHREADS, 1)
node_kernel(const float* __restrict__ emb,
            const float* __restrict__ bias,
            const float* __restrict__ We,
            int nn) {
    extern __shared__ char smraw[];
    const uint32_t smem = smem_u32(smraw);
    const int tid  = threadIdx.x;
    const int lane = tid & 31;
    const int wid  = tid >> 5;     // 0..15
    const int wm   = wid >> 2;     // 0..3  -> rows wm*32..
    const int wn   = wid & 3;      // 0..3  -> cols wn*64..
    const int row0 = blockIdx.x * BM;

    if (tid < 128) *reinterpret_cast<float*>(smraw + OFF_RED + tid * 4) = 0.f;
    if (tid < 256) {
        float2 v; v.x = bias[tid]; v.y = 0.5f * (We[tid] + We[tid + HID]);
        *reinterpret_cast<float2*>(smraw + OFF_BW + tid * 8) = v;
    }

    // ---- async stage loaders (no register staging) ----
    // A fp32: 128 rows x 64 floats = 32KB; 4 cp16 per thread
    auto cpA = [&](int s, int buf) {
        const int k0 = s * KB;
        #pragma unroll
        for (int i = 0; i < 4; ++i) {
            const int flat = tid + i * NTHREADS;       // 0..2047
            const int r = flat >> 4, ch = flat & 15;   // row, 4-float chunk
            int gr = row0 + r; if (gr >= nn) gr = nn - 1;  // clamp: junk rows unused
            cp16(smem + OFF_AF + buf * 32768 + r * 256 + ch * 16,
                 &emb[(size_t)gr * IN_DIM + k0 + ch * 4]);
        }
    };
    // B bf16: 64 k-rows x 256 n = 32KB; 4 cp16 per thread, swizzled dst
    auto cpB = [&](int s, int buf) {
        #pragma unroll
        for (int i = 0; i < 4; ++i) {
            const int flat = tid + i * NTHREADS;       // 0..2047
            const int kr = flat >> 5, ch = flat & 31;  // k-row, 8-elem chunk
            const uint32_t dst = smem + OFF_B + buf * 32768 + kr * 512 + ((ch ^ (kr & 7)) << 4);
            cp16(dst, &g_Wb[(size_t)(s * KB + kr) * HID + ch * 8]);
        }
        CP_COMMIT();
    };
    // convert own-copied fp32 chunks -> swizzled bf16 tile (no barrier needed:
    // each thread reads exactly the smem bytes its own cp.async wrote)
    auto convA = [&](int buf) {
        #pragma unroll
        for (int i = 0; i < 4; ++i) {
            const int flat = tid + i * NTHREADS;
            const int r = flat >> 4, ch = flat & 15;
            const float4 v = *reinterpret_cast<const float4*>(
                smraw + OFF_AF + buf * 32768 + r * 256 + ch * 16);
            uint2 t; t.x = pack_bf2(v.x, v.y); t.y = pack_bf2(v.z, v.w);
            const uint32_t off = (uint32_t)(r * 128 + (((ch >> 1) ^ (r & 7)) << 4) + (ch & 1) * 8);
            *reinterpret_cast<uint2*>(smraw + OFF_ABF + buf * 16384 + off) = t;
        }
    };

    float acc[2][8][4];
    #pragma unroll
    for (int i = 0; i < 2; ++i)
        #pragma unroll
        for (int j = 0; j < 8; ++j)
            acc[i][j][0] = acc[i][j][1] = acc[i][j][2] = acc[i][j][3] = 0.f;

    // ---- prologue: group(0)={A0,B0}, group(1)={A1,B1} ----
    cpA(0, 0); cpB(0, 0);          // cpB ends with COMMIT -> closes group 0
    cpA(1, 1); cpB(1, 1);          // closes group 1
    CP_WAIT(1);                    // group 0 retired
    convA(0);                      // Abf[0] ready (own data)
    __syncthreads();               // publish Abf[0], B[0]

    const int lr  = (lane & 7) + (lane & 8);   // ldmatrix row-within-pair
    const int lhi = (lane >> 4) & 1;           // second 8-chunk select

    #pragma unroll 1
    for (int s = 0; s < NS; ++s) {
        if (s + 2 < NS) {
            cpA(s + 2, s & 1);               // stage s+2 -> Af32[(s+2)&1 == s&1]
            cpB(s + 2, (s + 2) % 3);         // B[(s+2)%3]: last read at stage s-1
            CP_WAIT(1);                      // group(s+1) retired
        } else if (s + 1 < NS) {
            CP_WAIT(0);
        }
        if (s + 1 < NS) convA((s + 1) & 1);  // convert stage s+1 from Af32[(s+1)&1]

        const uint32_t aBase = smem + OFF_ABF + (s & 1) * 16384;
        const uint32_t bBase = smem + OFF_B + (s % 3) * 32768;

        #pragma unroll
        for (int kk = 0; kk < 4; ++kk) {
            const int k0 = kk * 16;
            uint32_t a[2][4];
            #pragma unroll
            for (int i = 0; i < 2; ++i) {
                const int mr = wm * 32 + i * 16 + lr;
                const int kc = (k0 >> 3) + lhi;
                ldsm_x4(a[i], aBase + mr * 128 + ((kc ^ (mr & 7)) << 4));
            }
            uint32_t b[4][4];
            #pragma unroll
            for (int j = 0; j < 4; ++j) {
                const int kr = k0 + lr;
                const int nc = wn * 8 + j * 2 + lhi;
                ldsm_x4t(b[j], bBase + kr * 512 + ((nc ^ (kr & 7)) << 4));
            }
            #pragma unroll
            for (int i = 0; i < 2; ++i)
                #pragma unroll
                for (int j = 0; j < 4; ++j) {
                    mma16816(acc[i][j * 2 + 0], a[i], b[j][0], b[j][1]);
                    mma16816(acc[i][j * 2 + 1], a[i], b[j][2], b[j][3]);
                }
        }

        if (s + 1 < NS) __syncthreads();     // publish convA(s+1) + B(s+1)
    }

    // ---- epilogue: p[m] = sum_n relu(D[m][n]+bias[n])*w_sym[n] ----
    const float2* bw = reinterpret_cast<const float2*>(smraw + OFF_BW);
    float* red = reinterpret_cast<float*>(smraw + OFF_RED);
    #pragma unroll
    for (int i = 0; i < 2; ++i) {
        float p0 = 0.f, p1 = 0.f;
        #pragma unroll
        for (int t = 0; t < 8; ++t) {
            const int ncol = wn * 64 + t * 8 + (lane & 3) * 2;
            const float2 w0 = bw[ncol], w1 = bw[ncol + 1];
            const float* c = acc[i][t];
            p0 += fmaxf(c[0] + w0.x, 0.f) * w0.y + fmaxf(c[1] + w1.x, 0.f) * w1.y;
            p1 += fmaxf(c[2] + w0.x, 0.f) * w0.y + fmaxf(c[3] + w1.x, 0.f) * w1.y;
        }
        p0 += __shfl_xor_sync(0xffffffffu, p0, 1);
        p0 += __shfl_xor_sync(0xffffffffu, p0, 2);
        p1 += __shfl_xor_sync(0xffffffffu, p1, 1);
        p1 += __shfl_xor_sync(0xffffffffu, p1, 2);
        if ((lane & 3) == 0) {
            const int r = wm * 32 + i * 16 + (lane >> 2);
            atomicAdd(&red[r], p0);
            atomicAdd(&red[r + 8], p1);
        }
    }
    __syncthreads();
    if (tid < BM) {
        const int gr = row0 + tid;
        if (gr < nn) g_s[gr] = red[tid];
    }
}

// sigmoid(log(eps/(1-eps)) + raw) == eps / (eps + (1-eps)*exp(-raw))
__global__ void edge_kernel(const int* __restrict__ e0,
                            const int* __restrict__ e1,
                            const float* __restrict__ u,
                            const float* __restrict__ be,
                            float* __restrict__ out,
                            int E) {
    const int i = blockIdx.x * blockDim.x + threadIdx.x;
    const int nv = E >> 2;
    if (i >= nv) {
        if (i == nv) {
            const float bb = be[0];
            for (int k = nv * 4; k < E; ++k) {
                const float raw = g_s[e0[k]] + g_s[e1[k]] + bb;
                const float uu = u[k];
                const float eps = fmaf(-0.9998f, uu, 0.9999f);
                const float ome = fmaf(0.9998f, uu, 0.0001f);
                out[k] = eps / fmaf(ome, __expf(-raw), eps);
            }
        }
        return;
    }
    const int4   a  = reinterpret_cast<const int4*>(e0)[i];
    const int4   b  = reinterpret_cast<const int4*>(e1)[i];
    const float4 uu = reinterpret_cast<const float4*>(u)[i];
    const float  bb = be[0];
    float4 r;
    {
        const float raw = g_s[a.x] + g_s[b.x] + bb;
        const float eps = fmaf(-0.9998f, uu.x, 0.9999f);
        const float ome = fmaf(0.9998f, uu.x, 0.0001f);
        r.x = eps / fmaf(ome, __expf(-raw), eps);
    }
    {
        const float raw = g_s[a.y] + g_s[b.y] + bb;
        const float eps = fmaf(-0.9998f, uu.y, 0.9999f);
        const float ome = fmaf(0.9998f, uu.y, 0.0001f);
        r.y = eps / fmaf(ome, __expf(-raw), eps);
    }
    {
        const float raw = g_s[a.z] + g_s[b.z] + bb;
        const float eps = fmaf(-0.9998f, uu.z, 0.9999f);
        const float ome = fmaf(0.9998f, uu.z, 0.0001f);
        r.z = eps / fmaf(ome, __expf(-raw), eps);
    }
    {
        const float raw = g_s[a.w] + g_s[b.w] + bb;
        const float eps = fmaf(-0.9998f, uu.w, 0.9999f);
        const float ome = fmaf(0.9998f, uu.w, 0.0001f);
        r.w = eps / fmaf(ome, __expf(-raw), eps);
    }
    reinterpret_cast<float4*>(out)[i] = r;
}

extern "C" void kernel_launch(void* const* d_in, const int* in_sizes, int n_in,
                              void* d_out, int out_size) {
    const float* emb   = (const float*)d_in[0];
    const int*   edges = (const int*)d_in[1];     // int32 (JAX x64 disabled)
    const float* u     = (const float*)d_in[2];
    const float* W     = (const float*)d_in[3];
    const float* b     = (const float*)d_in[4];
    const float* We    = (const float*)d_in[5];
    const float* be    = (const float*)d_in[6];
    float*       out   = (float*)d_out;

    const int nn = in_sizes[0] / IN_DIM;   // 50000
    const int E  = in_sizes[2];            // 800000

    convert_W<<<(IN_DIM * HID / 4 + 255) / 256, 256>>>((const float4*)W);

    cudaFuncSetAttribute(node_kernel, cudaFuncAttributeMaxDynamicSharedMemorySize, SMEM_TOTAL);
    node_kernel<<<(nn + BM - 1) / BM, NTHREADS, SMEM_TOTAL>>>(emb, b, We, nn);

    const int nv = (E >> 2) + 1;
    edge_kernel<<<(nv + 255) / 256, 256>>>(edges, edges + E, u, be, out, E);
}